// round 12
// baseline (speedup 1.0000x reference)
#include <cuda_runtime.h>
#include <cuda_fp16.h>
#include <cstdint>

// ---------------- problem constants ----------------
#define BB   2
#define L2C  1024
#define L1C  8192
#define L0C  65536
#define SC   (L2C + L1C + L0C)   // 74752
#define DC   256
#define EN   131                 // P entries per tap: 32 (val,dep) combos + 3*33 pos

// ---------------- scratch (__device__ globals) ----------------
__device__ __half g_W1[256 * 2048];
__device__ __half g_W2[256 * 1024];
__device__ float  g_Wt0[8 * 256 * 256];        // W0 transposed: [t][d][o]
__device__ float  g_P[8 * EN * 256];           // precomputed conv0 tables [t][e][o]
__device__ __half g_x1hi[BB * L1C * DC], g_x1lo[BB * L1C * DC];
__device__ __half g_x2hi[BB * L2C * DC], g_x2lo[BB * L2C * DC];
__device__ float  g_part[4 * BB * 1024 * 256]; // GEMM1 split-K partials
__device__ int    g_inv1[BB * L1C];            // y0 src row -> x1 target (-1 none)
__device__ int    g_inv2[BB * L2C];            // y1 src row -> x2 target (-1 none)
__device__ int    g_outdst[BB * 256];          // conv2 row -> out slot (-1 none)

// ---------------- helpers ----------------
__device__ __forceinline__ uint32_t smem_u32(const void* p) {
    uint32_t a;
    asm("{ .reg .u64 t; cvta.to.shared.u64 t, %1; cvt.u32.u64 %0, t; }" : "=r"(a) : "l"(p));
    return a;
}
__device__ __forceinline__ void split2h(float x, __half& h, __half& l) {
    h = __float2half(x);
    l = __float2half(x - __half2float(h));
}
__device__ __forceinline__ void cpasync16(uint32_t saddr, const void* gaddr) {
    asm volatile("cp.async.cg.shared.global [%0], [%1], 16;" :: "r"(saddr), "l"(gaddr));
}
__device__ __forceinline__ void ldsm4(uint32_t* r, uint32_t a) {
    asm volatile("ldmatrix.sync.aligned.m8n8.x4.shared.b16 {%0,%1,%2,%3}, [%4];"
                 : "=r"(r[0]), "=r"(r[1]), "=r"(r[2]), "=r"(r[3]) : "r"(a));
}
__device__ __forceinline__ void mma16816(float* d, const uint32_t* a, const uint32_t* b) {
    asm volatile(
        "mma.sync.aligned.m16n8k16.row.col.f32.f16.f16.f32 "
        "{%0,%1,%2,%3}, {%4,%5,%6,%7}, {%8,%9}, {%0,%1,%2,%3};"
        : "+f"(d[0]), "+f"(d[1]), "+f"(d[2]), "+f"(d[3])
        : "r"(a[0]), "r"(a[1]), "r"(a[2]), "r"(a[3]), "r"(b[0]), "r"(b[1]));
}

__device__ __forceinline__ int exscan1024(int v, int tid, int* sW, int* total) {
    int lane = tid & 31, w = tid >> 5;
    int x = v;
    #pragma unroll
    for (int o = 1; o < 32; o <<= 1) {
        int t = __shfl_up_sync(0xFFFFFFFFu, x, o);
        if (lane >= o) x += t;
    }
    if (lane == 31) sW[w] = x;
    __syncthreads();
    if (tid < 32) {
        int y = sW[lane];
        #pragma unroll
        for (int o = 1; o < 32; o <<= 1) {
            int t = __shfl_up_sync(0xFFFFFFFFu, y, o);
            if (lane >= o) y += t;
        }
        sW[lane] = y;
    }
    __syncthreads();
    int off = (w == 0) ? 0 : sW[w - 1];
    int tot = sW[31];
    __syncthreads();
    *total = tot;
    return off + x - v;
}

// ---------------- prep1: indices | W0 transpose | embed L1/L2 | wsplit | zero ----------------
#define IDX_NB 6
#define TRN_B0 6
#define TRN_NB 32
#define EMB_B0 (TRN_B0 + TRN_NB)          // 38
#define EMB_NB 2304                        // 18432 rows / 8
#define WSP_B0 (EMB_B0 + EMB_NB)           // 2342
#define WSP_NB 768                         // 786432 / 1024
#define ZER_B0 (WSP_B0 + WSP_NB)           // 3110
#define ZER_NB 8
#define PREP_GRID (ZER_B0 + ZER_NB)        // 3118
#define PREP_SMEM 66048

__global__ void __launch_bounds__(1024) k_prep1(
    const int* __restrict__ value, const int* __restrict__ depth,
    const int* __restrict__ position,
    const float* __restrict__ emb_val, const float* __restrict__ emb_dep,
    const float* __restrict__ emb_pos,
    const float* __restrict__ W0, const float* __restrict__ W1,
    const float* __restrict__ W2, float* __restrict__ out)
{
    extern __shared__ char dsm[];
    int bid = blockIdx.x, tid = threadIdx.x;

    if (bid >= ZER_B0) {
        float4 z = make_float4(0.f, 0.f, 0.f, 0.f);
        for (int i = (bid - ZER_B0) * 1024 + tid; i < 32768; i += ZER_NB * 1024)
            ((float4*)out)[i] = z;
        return;
    }
    if (bid >= WSP_B0) {
        // weight fp16 convert: Wk[o][t*256+d] = fp16(W[o,d,t])
        int idx = (bid - WSP_B0) * 1024 + tid;
        const float* W; __half* O; int sK;
        if (idx < 524288)      { W = W1; O = g_W1; sK = 8; }
        else                   { idx -= 524288; W = W2; O = g_W2; sK = 4; }
        int d = idx & 255;
        int rem = idx >> 8;
        int t = rem % sK;
        int o = rem / sK;
        O[o * (sK * 256) + t * 256 + d] = __float2half(W[(o * 256 + d) * sK + t]);
        return;
    }
    if (bid >= EMB_B0) {
        // embedding for L2 + L1 rows only -> default x2 / x1 (hi/lo fp16)
        int r = (bid - EMB_B0) * 8 + (tid >> 7);
        if (r >= BB * (L2C + L1C)) return;
        int b = r / (L2C + L1C);
        int lr = r - b * (L2C + L1C);
        long tok = (long)b * SC + lr;
        int d = (tid & 127) * 2;
        int v = value[tok], dep = depth[tok];
        const int* p = position + tok * 3;
        float2 e = *(const float2*)&emb_val[v * DC + d];
        float2 t2;
        t2 = *(const float2*)&emb_dep[dep * DC + d];              e.x += t2.x; e.y += t2.y;
        t2 = *(const float2*)&emb_pos[(0 * 33 + p[0]) * DC + d];  e.x += t2.x; e.y += t2.y;
        t2 = *(const float2*)&emb_pos[(1 * 33 + p[1]) * DC + d];  e.x += t2.x; e.y += t2.y;
        t2 = *(const float2*)&emb_pos[(2 * 33 + p[2]) * DC + d];  e.x += t2.x; e.y += t2.y;
        __half h0, l0, h1, l1;
        split2h(e.x, h0, l0); split2h(e.y, h1, l1);
        long dst;
        __half *HI, *LO;
        if (lr < L2C) { dst = ((long)b * L2C + lr) * DC + d;          HI = g_x2hi; LO = g_x2lo; }
        else          { dst = ((long)b * L1C + (lr - L2C)) * DC + d;  HI = g_x1hi; LO = g_x1lo; }
        *(__half2*)&HI[dst] = __halves2half2(h0, h1);
        *(__half2*)&LO[dst] = __halves2half2(l0, l1);
        return;
    }
    if (bid >= TRN_B0) {
        // W0 transpose -> Wt0[t][d][o], smem-tiled (o-tile 64, d-tile 32)
        float* ts = (float*)dsm;    // [64][257]
        int blk = bid - TRN_B0;
        int o0 = (blk >> 3) * 64;
        int d0 = (blk & 7) * 32;
        for (int i = tid; i < 64 * 256; i += 1024) {
            int ol = i >> 8, j = i & 255;            // j = dl*8 + t
            ts[ol * 257 + j] = W0[(o0 + ol) * 2048 + d0 * 8 + j];
        }
        __syncthreads();
        for (int i = tid; i < 64 * 256; i += 1024) {
            int td = i >> 6, ol = i & 63;
            int dl = td >> 3, t = td & 7;
            g_Wt0[(t * 256 + d0 + dl) * 256 + o0 + ol] = ts[ol * 257 + dl * 8 + t];
        }
        return;
    }

    // ---- indices: 6 blocks (b, sec) ----
    int* sOrder = (int*)dsm;            // 8192 ints
    int* sScan  = sOrder + 8192;        // 32 ints
    int b = bid / 3;
    int sec = bid % 3;
    const int* vb = value + (long)b * SC;

    if (sec == 0) {
        // sub1: sources = v0 heads (8192), targets = v1==2 (8192); build inv1[src]=tgt
        for (int i = tid; i < L1C; i += 1024) g_inv1[b * L1C + i] = -1;
        int base = tid * 8, local = 0;
        unsigned mask = 0;
        #pragma unroll
        for (int i = 0; i < 8; i++) {
            int p = (vb[L2C + L1C + (base + i) * 8] != 0);
            mask |= (unsigned)p << i; local += p;
        }
        int tot; int ex = exscan1024(local, tid, sScan, &tot);
        int rt = ex, rf = base - ex;
        #pragma unroll
        for (int i = 0; i < 8; i++) {
            int j = base + i;
            if ((mask >> i) & 1u) sOrder[rt++] = j;
            else                  sOrder[tot + rf++] = j;
        }
        __syncthreads();
        local = 0; mask = 0;
        #pragma unroll
        for (int i = 0; i < 8; i++) {
            int p = (vb[L2C + base + i] == 2);
            mask |= (unsigned)p << i; local += p;
        }
        ex = exscan1024(local, tid, sScan, &tot);
        int r = ex;
        #pragma unroll
        for (int i = 0; i < 8; i++) {
            int j = base + i;
            if ((mask >> i) & 1u) { g_inv1[b * L1C + sOrder[min(r, 8191)]] = j; r++; }
        }
    } else if (sec == 1) {
        // sub2: sources = v1 heads (1024), targets = v2==2 (1024); inv2[src]=tgt
        g_inv2[b * L2C + tid] = -1;
        int p = (vb[L2C + tid * 8] != 0);
        int tot; int ex = exscan1024(p, tid, sScan, &tot);
        if (p) sOrder[ex] = tid;
        else   sOrder[tot + tid - ex] = tid;
        __syncthreads();
        int q = (vb[tid] == 2);
        int ex2 = exscan1024(q, tid, sScan, &tot);
        if (q) g_inv2[b * L2C + sOrder[min(ex2, 1023)]] = tid;
    } else {
        // output compaction map
        int any = 0;
        #pragma unroll
        for (int t = 0; t < 8; t++) any |= (vb[L2C + tid * 8 + t] == 2);
        sOrder[tid] = any;
        __syncthreads();
        int p = (vb[tid] == 2);
        int tot; int ex = exscan1024(p, tid, sScan, &tot);
        int m2 = p ? sOrder[min(ex, 1023)] : 0;
        sOrder[2048 + tid] = m2;
        __syncthreads();
        int m2g = 0;
        if (tid < 256)
            m2g = sOrder[2048 + 4 * tid] | sOrder[2048 + 4 * tid + 1]
                | sOrder[2048 + 4 * tid + 2] | sOrder[2048 + 4 * tid + 3];
        int tot2; int ex2 = exscan1024((tid < 256 && m2g) ? 1 : 0, tid, sScan, &tot2);
        if (tid < 256) g_outdst[b * 256 + tid] = m2g ? ex2 : -1;
    }
}

// ---------------- prep2: P[t][e][o] = sum_d Wt0[t][d][o] * c[e][d] ----------------
__global__ void __launch_bounds__(256) k_prep2(
    const float* __restrict__ emb_val, const float* __restrict__ emb_dep,
    const float* __restrict__ emb_pos)
{
    __shared__ float sc[8][256];
    int t = blockIdx.x / 17;
    int e0 = (blockIdx.x % 17) * 8;
    int tid = threadIdx.x;

    for (int i = tid; i < 8 * 256; i += 256) {
        int ee = i >> 8, d = i & 255;
        int e = e0 + ee;
        float cv = 0.f;
        if (e < EN) {
            if (e < 32) cv = emb_val[(e >> 3) * 256 + d] + emb_dep[(e & 7) * 256 + d];
            else        cv = emb_pos[(e - 32) * 256 + d];
        }
        sc[ee][d] = cv;
    }
    __syncthreads();

    float acc[8];
    #pragma unroll
    for (int ee = 0; ee < 8; ee++) acc[ee] = 0.f;
    const float* wt = g_Wt0 + (long)t * 256 * 256 + tid;
    for (int d = 0; d < 256; d++) {
        float wv = wt[d * 256];
        #pragma unroll
        for (int ee = 0; ee < 8; ee++) acc[ee] += wv * sc[ee][d];
    }
    #pragma unroll
    for (int ee = 0; ee < 8; ee++) {
        int e = e0 + ee;
        if (e < EN) g_P[((long)t * EN + e) * 256 + tid] = acc[ee];
    }
}

// ---------------- k_y0: conv0-from-tables with smem-cached P column slice ----------------
// grid (8 row-chunks, 8 col-tiles, BB); 256 threads; smem = 8*131*32 floats = 134144 B.
#define Y0_SMEM (8 * EN * 32 * 4)
__global__ void __launch_bounds__(256) k_y0(
    const int* __restrict__ value, const int* __restrict__ depth,
    const int* __restrict__ position, const float* __restrict__ b0)
{
    extern __shared__ float sP[];            // [t][e][32]
    int tid = threadIdx.x;
    int b = blockIdx.z;
    int c0 = blockIdx.y * 32;
    int r0 = blockIdx.x * 1024;

    // load P slice: 8*131 rows of 32 floats (128B) each, via float4
    for (int j = tid; j < 8 * EN * 8; j += 256) {
        int te = j >> 3;
        int c4 = (j & 7) * 4;
        *(float4*)&sP[te * 32 + c4] = *(const float4*)&g_P[(long)te * 256 + c0 + c4];
    }
    __syncthreads();

    int rq = tid >> 3;            // 0..31: row within 32-row batch
    int cg = (tid & 7) * 4;       // 0,4,..,28: col offset within tile
    float4 bias = *(const float4*)&b0[c0 + cg];

    for (int it = 0; it < 32; it++) {
        int s = r0 + it * 32 + rq;                 // y0 source row
        int tgt = g_inv1[b * L1C + s];
        if (tgt < 0) continue;
        long tokbase = (long)b * SC + L2C + L1C + (long)s * 8;
        float4 acc = bias;
        #pragma unroll
        for (int t = 0; t < 8; t++) {
            long tok = tokbase + t;
            int v = value[tok], dep = depth[tok];
            const int* p = position + tok * 3;
            const float* Pt = sP + t * (EN * 32);
            float4 a0 = *(const float4*)&Pt[((v << 3) | dep) * 32 + cg];
            float4 a1 = *(const float4*)&Pt[(32 + p[0]) * 32 + cg];
            float4 a2 = *(const float4*)&Pt[(65 + p[1]) * 32 + cg];
            float4 a3 = *(const float4*)&Pt[(98 + p[2]) * 32 + cg];
            acc.x += a0.x + a1.x + a2.x + a3.x;
            acc.y += a0.y + a1.y + a2.y + a3.y;
            acc.z += a0.z + a1.z + a2.z + a3.z;
            acc.w += a0.w + a1.w + a2.w + a3.w;
        }
        __half h0, l0, h1, l1, h2, l2, h3, l3;
        split2h(acc.x, h0, l0); split2h(acc.y, h1, l1);
        split2h(acc.z, h2, l2); split2h(acc.w, h3, l3);
        long dst = ((long)b * L1C + tgt) * DC + c0 + cg;
        *(__half2*)&g_x1hi[dst]     = __halves2half2(h0, h1);
        *(__half2*)&g_x1hi[dst + 2] = __halves2half2(h2, h3);
        *(__half2*)&g_x1lo[dst]     = __halves2half2(l0, l1);
        *(__half2*)&g_x1lo[dst + 2] = __halves2half2(l2, l3);
    }
}

// ---------------- 2-term fp16 split GEMM via mma.sync ----------------
// OUTM=2: fp32 scatter rows via rowmap (+bias). OUTM=3: split-K fp32 partials (no bias).
template <int BM, int BN, int KK, int LDK, int STAGES, int OUTM>
__global__ void __launch_bounds__(256, 2) k_gemm(
    const __half* __restrict__ Ahi, const __half* __restrict__ Alo, long strideA,
    const __half* __restrict__ Bh, const float* __restrict__ bias,
    float* __restrict__ Cf, const int* __restrict__ rowmap, long strideC)
{
    constexpr int NC = KK / 64;
    constexpr int P = STAGES - 1;
    constexpr int ABYTES = BM * 128;
    constexpr int BBYTES = BN * 128;
    constexpr int STAGE = 2 * ABYTES + BBYTES;
    constexpr int WM = BM / 2, WN = BN / 4;
    constexpr int MT = WM / 16, NP = WN / 16;
    constexpr int TOTROWS = 2 * BM + BN;

    extern __shared__ __align__(1024) char smem[];
    uint32_t sb = smem_u32(smem);

    int tid = threadIdx.x;
    int lane = tid & 31, wid = tid >> 5;
    int wm0 = (wid >> 2) * WM;
    int wn0 = (wid & 3) * WN;
    int m0 = blockIdx.x * BM;
    int b = blockIdx.z;
    int n0, koff;
    if (OUTM == 3) { n0 = 0; koff = blockIdx.y * KK; }
    else           { n0 = blockIdx.y * BN; koff = 0; }

    const __half* Ah = Ahi + (long)b * strideA;
    const __half* Al = Alo + (long)b * strideA;

    float acc[MT][2 * NP][4];
    #pragma unroll
    for (int i = 0; i < MT; i++)
        #pragma unroll
        for (int j = 0; j < 2 * NP; j++)
            #pragma unroll
            for (int k = 0; k < 4; k++) acc[i][j][k] = 0.f;

    auto load_chunk = [&](int c) {
        uint32_t st = sb + (uint32_t)((c % STAGES) * STAGE);
        long k0 = (long)koff + c * 64;
        #pragma unroll
        for (int i = tid; i < TOTROWS * 8; i += 256) {
            int r = i >> 3, seg = i & 7;
            const __half* g;
            uint32_t base;
            if (r < BM)          { g = Ah + (long)(m0 + r) * LDK;                  base = st; }
            else if (r < 2 * BM) { int rr = r - BM;     g = Al + (long)(m0 + rr) * LDK; base = st + ABYTES;     r = rr; }
            else                 { int rr = r - 2 * BM; g = Bh + (long)(n0 + rr) * LDK; base = st + 2 * ABYTES; r = rr; }
            uint32_t off = (uint32_t)(r * 128 + seg * 16);
            uint32_t dst = base + (off ^ (uint32_t)((r & 7) << 4));
            cpasync16(dst, g + k0 + seg * 8);
        }
        asm volatile("cp.async.commit_group;" ::: "memory");
    };

    #pragma unroll
    for (int pc = 0; pc < P && pc < NC; pc++) load_chunk(pc);

    const uint32_t xorm = (uint32_t)((lane & 7) << 4);
    const uint32_t a_lrow = (uint32_t)(lane & 15);
    const uint32_t a_khalf = (uint32_t)(lane & 16);
    const uint32_t b_lrow = (uint32_t)((lane & 7) | ((lane & 16) >> 1));
    const uint32_t b_khalf = (uint32_t)((lane & 8) << 1);

    for (int c = 0; c < NC; ++c) {
        if (c + P < NC) {
            load_chunk(c + P);
            asm volatile("cp.async.wait_group %0;" :: "n"(P) : "memory");
        } else {
            asm volatile("cp.async.wait_group 0;" ::: "memory");
        }
        __syncthreads();

        uint32_t st = sb + (uint32_t)((c % STAGES) * STAGE);
        #pragma unroll
        for (int ks = 0; ks < 4; ks++) {
            uint32_t a[2][MT][4], bf[NP][4];
            #pragma unroll
            for (int mi = 0; mi < MT; mi++) {
                uint32_t off = (uint32_t)((wm0 + mi * 16 + a_lrow) * 128) + (uint32_t)(ks * 32) + a_khalf;
                ldsm4(a[0][mi], st + (off ^ xorm));
                ldsm4(a[1][mi], st + ABYTES + (off ^ xorm));
            }
            #pragma unroll
            for (int pi = 0; pi < NP; pi++) {
                uint32_t off = (uint32_t)((wn0 + pi * 16 + b_lrow) * 128) + (uint32_t)(ks * 32) + b_khalf;
                ldsm4(bf[pi], st + 2 * ABYTES + (off ^ xorm));
            }
            #pragma unroll
            for (int mi = 0; mi < MT; mi++)
                #pragma unroll
                for (int pi = 0; pi < NP; pi++) {
                    mma16816(acc[mi][2 * pi],     a[0][mi], &bf[pi][0]);
                    mma16816(acc[mi][2 * pi + 1], a[0][mi], &bf[pi][2]);
                    mma16816(acc[mi][2 * pi],     a[1][mi], &bf[pi][0]);
                    mma16816(acc[mi][2 * pi + 1], a[1][mi], &bf[pi][2]);
                }
        }
        __syncthreads();
    }

    // epilogue
    int g4 = lane >> 2, t4 = lane & 3;
    #pragma unroll
    for (int mi = 0; mi < MT; mi++) {
        #pragma unroll
        for (int ni = 0; ni < 2 * NP; ni++) {
            int m = m0 + wm0 + mi * 16 + g4;
            int col = n0 + wn0 + ni * 8 + t4 * 2;
            if (OUTM == 3) {
                long base0 = (((long)blockIdx.y * BB + b) * 1024 + m) * 256 + col;
                *(float2*)&Cf[base0] = make_float2(acc[mi][ni][0], acc[mi][ni][1]);
                *(float2*)&Cf[base0 + 8 * 256] = make_float2(acc[mi][ni][2], acc[mi][ni][3]);
            } else {
                float bx = bias[col], by = bias[col + 1];
                int d0 = rowmap[b * 256 + m];
                int d1 = rowmap[b * 256 + m + 8];
                if (d0 >= 0)
                    *(float2*)&Cf[(long)b * strideC + (long)d0 * 256 + col] =
                        make_float2(acc[mi][ni][0] + bx, acc[mi][ni][1] + by);
                if (d1 >= 0)
                    *(float2*)&Cf[(long)b * strideC + (long)d1 * 256 + col] =
                        make_float2(acc[mi][ni][2] + bx, acc[mi][ni][3] + by);
            }
        }
    }
}

// ---------------- k_red1: reduce GEMM1 partials + bias, scatter into x2 ----------------
__global__ void __launch_bounds__(128) k_red1(const float* __restrict__ b1) {
    int row = blockIdx.x, b = blockIdx.y;
    int tgt = g_inv2[b * L2C + row];
    if (tgt < 0) return;
    int col = threadIdx.x * 2;
    float2 s = make_float2(b1[col], b1[col + 1]);
    #pragma unroll
    for (int sp = 0; sp < 4; sp++) {
        float2 v = *(const float2*)&g_part[(((long)sp * BB + b) * 1024 + row) * 256 + col];
        s.x += v.x; s.y += v.y;
    }
    __half h0, l0, h1, l1;
    split2h(s.x, h0, l0); split2h(s.y, h1, l1);
    long dst = ((long)b * L2C + tgt) * DC + col;
    *(__half2*)&g_x2hi[dst] = __halves2half2(h0, h1);
    *(__half2*)&g_x2lo[dst] = __halves2half2(l0, l1);
}

// ---------------- launch ----------------
extern "C" void kernel_launch(void* const* d_in, const int* in_sizes, int n_in,
                              void* d_out, int out_size) {
    (void)in_sizes; (void)n_in; (void)out_size;
    const int*   value    = (const int*)d_in[0];
    const int*   depth    = (const int*)d_in[1];
    const int*   position = (const int*)d_in[2];
    const float* emb_val  = (const float*)d_in[3];
    const float* emb_dep  = (const float*)d_in[4];
    const float* emb_pos  = (const float*)d_in[5];
    const float* W0 = (const float*)d_in[6];
    const float* b0 = (const float*)d_in[7];
    const float* W1 = (const float*)d_in[8];
    const float* b1 = (const float*)d_in[9];
    const float* W2 = (const float*)d_in[10];
    const float* b2 = (const float*)d_in[11];
    float* out = (float*)d_out;

    __half *w1, *w2, *x1h, *x1l, *x2h, *x2l;
    float *part;
    int *odst;
    cudaGetSymbolAddress((void**)&w1, g_W1);
    cudaGetSymbolAddress((void**)&w2, g_W2);
    cudaGetSymbolAddress((void**)&x1h, g_x1hi); cudaGetSymbolAddress((void**)&x1l, g_x1lo);
    cudaGetSymbolAddress((void**)&x2h, g_x2hi); cudaGetSymbolAddress((void**)&x2l, g_x2lo);
    cudaGetSymbolAddress((void**)&part, g_part);
    cudaGetSymbolAddress((void**)&odst, g_outdst);

    const int SMEM1 = 2 * ((2 * 64 + 256) * 128);   // 98304 (BM64,BN256, 2 stages)
    const int SMEM2 = 4 * ((2 * 64 + 64) * 128);    // 98304 (64x64, 4 stages)
    cudaFuncSetAttribute(k_prep1, cudaFuncAttributeMaxDynamicSharedMemorySize, PREP_SMEM);
    cudaFuncSetAttribute(k_y0, cudaFuncAttributeMaxDynamicSharedMemorySize, Y0_SMEM);
    cudaFuncSetAttribute(k_gemm<64, 256, 512, 2048, 2, 3>, cudaFuncAttributeMaxDynamicSharedMemorySize, SMEM1);
    cudaFuncSetAttribute(k_gemm<64, 64, 1024, 1024, 4, 2>, cudaFuncAttributeMaxDynamicSharedMemorySize, SMEM2);

    // 1. prep1: indices + W0 transpose + embed(L1,L2) + W1/W2 fp16 + zero out
    k_prep1<<<PREP_GRID, 1024, PREP_SMEM>>>(value, depth, position,
                                            emb_val, emb_dep, emb_pos, W0, W1, W2, out);
    // 2. prep2: P tables (conv0 absorbed into embedding tables)
    k_prep2<<<8 * 17, 256>>>(emb_val, emb_dep, emb_pos);
    // 3. y0 via smem-cached table gathers, scattered directly into x1
    k_y0<<<dim3(8, 8, BB), 256, Y0_SMEM>>>(value, depth, position, b0);
    // 4. GEMM1: 1024 x 2048 x 256 per batch, split-K x4 -> partials
    k_gemm<64, 256, 512, 2048, 2, 3><<<dim3(16, 4, BB), 256, SMEM1>>>(
        x1h, x1l, (long)L1C * DC, w1, nullptr, part, nullptr, 0);
    // 5. reduce partials + b1, scatter into x2
    k_red1<<<dim3(1024, BB), 128>>>(b1);
    // 6. GEMM2: 256 x 1024 x 256 per batch, scatter rows into out
    k_gemm<64, 64, 1024, 1024, 4, 2><<<dim3(4, 4, BB), 256, SMEM2>>>(
        x2h, x2l, (long)L2C * DC, w2, b2, out, odst, (long)(256 * 256));
}

// round 13
// speedup vs baseline: 1.1354x; 1.1354x over previous
#include <cuda_runtime.h>
#include <cuda_fp16.h>
#include <cstdint>

// ---------------- problem constants ----------------
#define BB   2
#define L2C  1024
#define L1C  8192
#define L0C  65536
#define SC   (L2C + L1C + L0C)   // 74752
#define DC   256
#define EN   131                 // P entries per tap: 32 (val,dep) combos + 3*33 pos

// ---------------- scratch (__device__ globals) ----------------
__device__ __half g_W1[256 * 2048];
__device__ __half g_W2[256 * 1024];
__device__ float  g_Wt0[8 * 256 * 256];        // W0 transposed: [t][d][o]
__device__ __half g_P[8 * EN * 256];           // precomputed conv0 tables [t][e][o], fp16
__device__ __half g_x1hi[BB * L1C * DC], g_x1lo[BB * L1C * DC];
__device__ __half g_x2hi[BB * L2C * DC], g_x2lo[BB * L2C * DC];
__device__ float  g_part[4 * BB * 1024 * 256]; // GEMM1 split-K partials
__device__ int    g_inv1[BB * L1C];            // y0 src row -> x1 target (-1 none)
__device__ int    g_inv2[BB * L2C];            // y1 src row -> x2 target (-1 none)
__device__ int    g_outdst[BB * 256];          // conv2 row -> out slot (-1 none)

// ---------------- helpers ----------------
__device__ __forceinline__ uint32_t smem_u32(const void* p) {
    uint32_t a;
    asm("{ .reg .u64 t; cvta.to.shared.u64 t, %1; cvt.u32.u64 %0, t; }" : "=r"(a) : "l"(p));
    return a;
}
__device__ __forceinline__ void split2h(float x, __half& h, __half& l) {
    h = __float2half(x);
    l = __float2half(x - __half2float(h));
}
__device__ __forceinline__ void cpasync16(uint32_t saddr, const void* gaddr) {
    asm volatile("cp.async.cg.shared.global [%0], [%1], 16;" :: "r"(saddr), "l"(gaddr));
}
__device__ __forceinline__ void ldsm4(uint32_t* r, uint32_t a) {
    asm volatile("ldmatrix.sync.aligned.m8n8.x4.shared.b16 {%0,%1,%2,%3}, [%4];"
                 : "=r"(r[0]), "=r"(r[1]), "=r"(r[2]), "=r"(r[3]) : "r"(a));
}
__device__ __forceinline__ void mma16816(float* d, const uint32_t* a, const uint32_t* b) {
    asm volatile(
        "mma.sync.aligned.m16n8k16.row.col.f32.f16.f16.f32 "
        "{%0,%1,%2,%3}, {%4,%5,%6,%7}, {%8,%9}, {%0,%1,%2,%3};"
        : "+f"(d[0]), "+f"(d[1]), "+f"(d[2]), "+f"(d[3])
        : "r"(a[0]), "r"(a[1]), "r"(a[2]), "r"(a[3]), "r"(b[0]), "r"(b[1]));
}

__device__ __forceinline__ int exscan1024(int v, int tid, int* sW, int* total) {
    int lane = tid & 31, w = tid >> 5;
    int x = v;
    #pragma unroll
    for (int o = 1; o < 32; o <<= 1) {
        int t = __shfl_up_sync(0xFFFFFFFFu, x, o);
        if (lane >= o) x += t;
    }
    if (lane == 31) sW[w] = x;
    __syncthreads();
    if (tid < 32) {
        int y = sW[lane];
        #pragma unroll
        for (int o = 1; o < 32; o <<= 1) {
            int t = __shfl_up_sync(0xFFFFFFFFu, y, o);
            if (lane >= o) y += t;
        }
        sW[lane] = y;
    }
    __syncthreads();
    int off = (w == 0) ? 0 : sW[w - 1];
    int tot = sW[31];
    __syncthreads();
    *total = tot;
    return off + x - v;
}

// ---------------- prep1: indices | W0 transpose | embed L1/L2 | wsplit | zero ----------------
#define IDX_NB 6
#define TRN_B0 6
#define TRN_NB 32
#define EMB_B0 (TRN_B0 + TRN_NB)          // 38
#define EMB_NB 2304                        // 18432 rows / 8
#define WSP_B0 (EMB_B0 + EMB_NB)           // 2342
#define WSP_NB 768                         // 786432 / 1024
#define ZER_B0 (WSP_B0 + WSP_NB)           // 3110
#define ZER_NB 8
#define PREP_GRID (ZER_B0 + ZER_NB)        // 3118
#define PREP_SMEM 66048

__global__ void __launch_bounds__(1024) k_prep1(
    const int* __restrict__ value, const int* __restrict__ depth,
    const int* __restrict__ position,
    const float* __restrict__ emb_val, const float* __restrict__ emb_dep,
    const float* __restrict__ emb_pos,
    const float* __restrict__ W0, const float* __restrict__ W1,
    const float* __restrict__ W2, float* __restrict__ out)
{
    extern __shared__ char dsm[];
    int bid = blockIdx.x, tid = threadIdx.x;

    if (bid >= ZER_B0) {
        float4 z = make_float4(0.f, 0.f, 0.f, 0.f);
        for (int i = (bid - ZER_B0) * 1024 + tid; i < 32768; i += ZER_NB * 1024)
            ((float4*)out)[i] = z;
        return;
    }
    if (bid >= WSP_B0) {
        // weight fp16 convert: Wk[o][t*256+d] = fp16(W[o,d,t])
        int idx = (bid - WSP_B0) * 1024 + tid;
        const float* W; __half* O; int sK;
        if (idx < 524288)      { W = W1; O = g_W1; sK = 8; }
        else                   { idx -= 524288; W = W2; O = g_W2; sK = 4; }
        int d = idx & 255;
        int rem = idx >> 8;
        int t = rem % sK;
        int o = rem / sK;
        O[o * (sK * 256) + t * 256 + d] = __float2half(W[(o * 256 + d) * sK + t]);
        return;
    }
    if (bid >= EMB_B0) {
        // embedding for L2 + L1 rows only -> default x2 / x1 (hi/lo fp16)
        int r = (bid - EMB_B0) * 8 + (tid >> 7);
        if (r >= BB * (L2C + L1C)) return;
        int b = r / (L2C + L1C);
        int lr = r - b * (L2C + L1C);
        long tok = (long)b * SC + lr;
        int d = (tid & 127) * 2;
        int v = value[tok], dep = depth[tok];
        const int* p = position + tok * 3;
        float2 e = *(const float2*)&emb_val[v * DC + d];
        float2 t2;
        t2 = *(const float2*)&emb_dep[dep * DC + d];              e.x += t2.x; e.y += t2.y;
        t2 = *(const float2*)&emb_pos[(0 * 33 + p[0]) * DC + d];  e.x += t2.x; e.y += t2.y;
        t2 = *(const float2*)&emb_pos[(1 * 33 + p[1]) * DC + d];  e.x += t2.x; e.y += t2.y;
        t2 = *(const float2*)&emb_pos[(2 * 33 + p[2]) * DC + d];  e.x += t2.x; e.y += t2.y;
        __half h0, l0, h1, l1;
        split2h(e.x, h0, l0); split2h(e.y, h1, l1);
        long dst;
        __half *HI, *LO;
        if (lr < L2C) { dst = ((long)b * L2C + lr) * DC + d;          HI = g_x2hi; LO = g_x2lo; }
        else          { dst = ((long)b * L1C + (lr - L2C)) * DC + d;  HI = g_x1hi; LO = g_x1lo; }
        *(__half2*)&HI[dst] = __halves2half2(h0, h1);
        *(__half2*)&LO[dst] = __halves2half2(l0, l1);
        return;
    }
    if (bid >= TRN_B0) {
        // W0 transpose -> Wt0[t][d][o], smem-tiled (o-tile 64, d-tile 32)
        float* ts = (float*)dsm;    // [64][257]
        int blk = bid - TRN_B0;
        int o0 = (blk >> 3) * 64;
        int d0 = (blk & 7) * 32;
        for (int i = tid; i < 64 * 256; i += 1024) {
            int ol = i >> 8, j = i & 255;            // j = dl*8 + t
            ts[ol * 257 + j] = W0[(o0 + ol) * 2048 + d0 * 8 + j];
        }
        __syncthreads();
        for (int i = tid; i < 64 * 256; i += 1024) {
            int td = i >> 6, ol = i & 63;
            int dl = td >> 3, t = td & 7;
            g_Wt0[(t * 256 + d0 + dl) * 256 + o0 + ol] = ts[ol * 257 + dl * 8 + t];
        }
        return;
    }

    // ---- indices: 6 blocks (b, sec) ----
    int* sOrder = (int*)dsm;            // 8192 ints
    int* sScan  = sOrder + 8192;        // 32 ints
    int b = bid / 3;
    int sec = bid % 3;
    const int* vb = value + (long)b * SC;

    if (sec == 0) {
        // sub1: sources = v0 heads (8192), targets = v1==2 (8192); build inv1[src]=tgt
        for (int i = tid; i < L1C; i += 1024) g_inv1[b * L1C + i] = -1;
        int base = tid * 8, local = 0;
        unsigned mask = 0;
        #pragma unroll
        for (int i = 0; i < 8; i++) {
            int p = (vb[L2C + L1C + (base + i) * 8] != 0);
            mask |= (unsigned)p << i; local += p;
        }
        int tot; int ex = exscan1024(local, tid, sScan, &tot);
        int rt = ex, rf = base - ex;
        #pragma unroll
        for (int i = 0; i < 8; i++) {
            int j = base + i;
            if ((mask >> i) & 1u) sOrder[rt++] = j;
            else                  sOrder[tot + rf++] = j;
        }
        __syncthreads();
        local = 0; mask = 0;
        #pragma unroll
        for (int i = 0; i < 8; i++) {
            int p = (vb[L2C + base + i] == 2);
            mask |= (unsigned)p << i; local += p;
        }
        ex = exscan1024(local, tid, sScan, &tot);
        int r = ex;
        #pragma unroll
        for (int i = 0; i < 8; i++) {
            int j = base + i;
            if ((mask >> i) & 1u) { g_inv1[b * L1C + sOrder[min(r, 8191)]] = j; r++; }
        }
    } else if (sec == 1) {
        // sub2: sources = v1 heads (1024), targets = v2==2 (1024); inv2[src]=tgt
        g_inv2[b * L2C + tid] = -1;
        int p = (vb[L2C + tid * 8] != 0);
        int tot; int ex = exscan1024(p, tid, sScan, &tot);
        if (p) sOrder[ex] = tid;
        else   sOrder[tot + tid - ex] = tid;
        __syncthreads();
        int q = (vb[tid] == 2);
        int ex2 = exscan1024(q, tid, sScan, &tot);
        if (q) g_inv2[b * L2C + sOrder[min(ex2, 1023)]] = tid;
    } else {
        // output compaction map
        int any = 0;
        #pragma unroll
        for (int t = 0; t < 8; t++) any |= (vb[L2C + tid * 8 + t] == 2);
        sOrder[tid] = any;
        __syncthreads();
        int p = (vb[tid] == 2);
        int tot; int ex = exscan1024(p, tid, sScan, &tot);
        int m2 = p ? sOrder[min(ex, 1023)] : 0;
        sOrder[2048 + tid] = m2;
        __syncthreads();
        int m2g = 0;
        if (tid < 256)
            m2g = sOrder[2048 + 4 * tid] | sOrder[2048 + 4 * tid + 1]
                | sOrder[2048 + 4 * tid + 2] | sOrder[2048 + 4 * tid + 3];
        int tot2; int ex2 = exscan1024((tid < 256 && m2g) ? 1 : 0, tid, sScan, &tot2);
        if (tid < 256) g_outdst[b * 256 + tid] = m2g ? ex2 : -1;
    }
}

// ---------------- prep2: P[t][e][o] = fp16( sum_d Wt0[t][d][o] * c[e][d] ) ----------------
__global__ void __launch_bounds__(256) k_prep2(
    const float* __restrict__ emb_val, const float* __restrict__ emb_dep,
    const float* __restrict__ emb_pos)
{
    __shared__ float sc[8][256];
    int t = blockIdx.x / 17;
    int e0 = (blockIdx.x % 17) * 8;
    int tid = threadIdx.x;

    for (int i = tid; i < 8 * 256; i += 256) {
        int ee = i >> 8, d = i & 255;
        int e = e0 + ee;
        float cv = 0.f;
        if (e < EN) {
            if (e < 32) cv = emb_val[(e >> 3) * 256 + d] + emb_dep[(e & 7) * 256 + d];
            else        cv = emb_pos[(e - 32) * 256 + d];
        }
        sc[ee][d] = cv;
    }
    __syncthreads();

    float acc[8];
    #pragma unroll
    for (int ee = 0; ee < 8; ee++) acc[ee] = 0.f;
    const float* wt = g_Wt0 + (long)t * 256 * 256 + tid;
    for (int d = 0; d < 256; d++) {
        float wv = wt[d * 256];
        #pragma unroll
        for (int ee = 0; ee < 8; ee++) acc[ee] += wv * sc[ee][d];
    }
    #pragma unroll
    for (int ee = 0; ee < 8; ee++) {
        int e = e0 + ee;
        if (e < EN) g_P[((long)t * EN + e) * 256 + tid] = __float2half(acc[ee]);
    }
}

// ---------------- k_y0: fused conv0 from fp16 tables, scattered into x1 ----------------
__global__ void __launch_bounds__(256) k_y0(
    const int* __restrict__ value, const int* __restrict__ depth,
    const int* __restrict__ position, const float* __restrict__ b0)
{
    int b = blockIdx.y;
    int hf = threadIdx.x >> 7;
    int lane = threadIdx.x & 127;
    int col = lane * 2;
    float2 bias = *(const float2*)&b0[col];

    #pragma unroll
    for (int j = 0; j < 4; j++) {
        int s = blockIdx.x * 8 + hf * 4 + j;              // source row in y0 (0..8191)
        int tgt = g_inv1[b * L1C + s];
        if (tgt < 0) continue;
        long tokbase = (long)b * SC + L2C + L1C + (long)s * 8;
        float2 acc = bias;
        #pragma unroll
        for (int t = 0; t < 8; t++) {
            long tok = tokbase + t;
            int v = value[tok], dep = depth[tok];
            const int* p = position + tok * 3;
            const __half* Pt = g_P + (long)t * EN * 256;
            float2 a0 = __half22float2(*(const __half2*)&Pt[((v << 3) | dep) * 256 + col]);
            float2 a1 = __half22float2(*(const __half2*)&Pt[(32 + p[0]) * 256 + col]);
            float2 a2 = __half22float2(*(const __half2*)&Pt[(65 + p[1]) * 256 + col]);
            float2 a3 = __half22float2(*(const __half2*)&Pt[(98 + p[2]) * 256 + col]);
            acc.x += a0.x + a1.x + a2.x + a3.x;
            acc.y += a0.y + a1.y + a2.y + a3.y;
        }
        __half h0, l0, h1, l1;
        split2h(acc.x, h0, l0); split2h(acc.y, h1, l1);
        long dst = ((long)b * L1C + tgt) * DC + col;
        *(__half2*)&g_x1hi[dst] = __halves2half2(h0, h1);
        *(__half2*)&g_x1lo[dst] = __halves2half2(l0, l1);
    }
}

// ---------------- 2-term fp16 split GEMM via mma.sync ----------------
// OUTM=2: fp32 scatter rows via rowmap (+bias). OUTM=3: split-K fp32 partials (no bias).
template <int BM, int BN, int KK, int LDK, int STAGES, int OUTM>
__global__ void __launch_bounds__(256, 2) k_gemm(
    const __half* __restrict__ Ahi, const __half* __restrict__ Alo, long strideA,
    const __half* __restrict__ Bh, const float* __restrict__ bias,
    float* __restrict__ Cf, const int* __restrict__ rowmap, long strideC)
{
    constexpr int NC = KK / 64;
    constexpr int P = STAGES - 1;
    constexpr int ABYTES = BM * 128;
    constexpr int BBYTES = BN * 128;
    constexpr int STAGE = 2 * ABYTES + BBYTES;
    constexpr int WM = BM / 2, WN = BN / 4;
    constexpr int MT = WM / 16, NP = WN / 16;
    constexpr int TOTROWS = 2 * BM + BN;

    extern __shared__ __align__(1024) char smem[];
    uint32_t sb = smem_u32(smem);

    int tid = threadIdx.x;
    int lane = tid & 31, wid = tid >> 5;
    int wm0 = (wid >> 2) * WM;
    int wn0 = (wid & 3) * WN;
    int m0 = blockIdx.x * BM;
    int b = blockIdx.z;
    int n0, koff;
    if (OUTM == 3) { n0 = 0; koff = blockIdx.y * KK; }
    else           { n0 = blockIdx.y * BN; koff = 0; }

    const __half* Ah = Ahi + (long)b * strideA;
    const __half* Al = Alo + (long)b * strideA;

    float acc[MT][2 * NP][4];
    #pragma unroll
    for (int i = 0; i < MT; i++)
        #pragma unroll
        for (int j = 0; j < 2 * NP; j++)
            #pragma unroll
            for (int k = 0; k < 4; k++) acc[i][j][k] = 0.f;

    auto load_chunk = [&](int c) {
        uint32_t st = sb + (uint32_t)((c % STAGES) * STAGE);
        long k0 = (long)koff + c * 64;
        #pragma unroll
        for (int i = tid; i < TOTROWS * 8; i += 256) {
            int r = i >> 3, seg = i & 7;
            const __half* g;
            uint32_t base;
            if (r < BM)          { g = Ah + (long)(m0 + r) * LDK;                  base = st; }
            else if (r < 2 * BM) { int rr = r - BM;     g = Al + (long)(m0 + rr) * LDK; base = st + ABYTES;     r = rr; }
            else                 { int rr = r - 2 * BM; g = Bh + (long)(n0 + rr) * LDK; base = st + 2 * ABYTES; r = rr; }
            uint32_t off = (uint32_t)(r * 128 + seg * 16);
            uint32_t dst = base + (off ^ (uint32_t)((r & 7) << 4));
            cpasync16(dst, g + k0 + seg * 8);
        }
        asm volatile("cp.async.commit_group;" ::: "memory");
    };

    #pragma unroll
    for (int pc = 0; pc < P && pc < NC; pc++) load_chunk(pc);

    const uint32_t xorm = (uint32_t)((lane & 7) << 4);
    const uint32_t a_lrow = (uint32_t)(lane & 15);
    const uint32_t a_khalf = (uint32_t)(lane & 16);
    const uint32_t b_lrow = (uint32_t)((lane & 7) | ((lane & 16) >> 1));
    const uint32_t b_khalf = (uint32_t)((lane & 8) << 1);

    for (int c = 0; c < NC; ++c) {
        if (c + P < NC) {
            load_chunk(c + P);
            asm volatile("cp.async.wait_group %0;" :: "n"(P) : "memory");
        } else {
            asm volatile("cp.async.wait_group 0;" ::: "memory");
        }
        __syncthreads();

        uint32_t st = sb + (uint32_t)((c % STAGES) * STAGE);
        #pragma unroll
        for (int ks = 0; ks < 4; ks++) {
            uint32_t a[2][MT][4], bf[NP][4];
            #pragma unroll
            for (int mi = 0; mi < MT; mi++) {
                uint32_t off = (uint32_t)((wm0 + mi * 16 + a_lrow) * 128) + (uint32_t)(ks * 32) + a_khalf;
                ldsm4(a[0][mi], st + (off ^ xorm));
                ldsm4(a[1][mi], st + ABYTES + (off ^ xorm));
            }
            #pragma unroll
            for (int pi = 0; pi < NP; pi++) {
                uint32_t off = (uint32_t)((wn0 + pi * 16 + b_lrow) * 128) + (uint32_t)(ks * 32) + b_khalf;
                ldsm4(bf[pi], st + 2 * ABYTES + (off ^ xorm));
            }
            #pragma unroll
            for (int mi = 0; mi < MT; mi++)
                #pragma unroll
                for (int pi = 0; pi < NP; pi++) {
                    mma16816(acc[mi][2 * pi],     a[0][mi], &bf[pi][0]);
                    mma16816(acc[mi][2 * pi + 1], a[0][mi], &bf[pi][2]);
                    mma16816(acc[mi][2 * pi],     a[1][mi], &bf[pi][0]);
                    mma16816(acc[mi][2 * pi + 1], a[1][mi], &bf[pi][2]);
                }
        }
        __syncthreads();
    }

    // epilogue
    int g4 = lane >> 2, t4 = lane & 3;
    #pragma unroll
    for (int mi = 0; mi < MT; mi++) {
        #pragma unroll
        for (int ni = 0; ni < 2 * NP; ni++) {
            int m = m0 + wm0 + mi * 16 + g4;
            int col = n0 + wn0 + ni * 8 + t4 * 2;
            if (OUTM == 3) {
                long base0 = (((long)blockIdx.y * BB + b) * 1024 + m) * 256 + col;
                *(float2*)&Cf[base0] = make_float2(acc[mi][ni][0], acc[mi][ni][1]);
                *(float2*)&Cf[base0 + 8 * 256] = make_float2(acc[mi][ni][2], acc[mi][ni][3]);
            } else {
                float bx = bias[col], by = bias[col + 1];
                int d0 = rowmap[b * 256 + m];
                int d1 = rowmap[b * 256 + m + 8];
                if (d0 >= 0)
                    *(float2*)&Cf[(long)b * strideC + (long)d0 * 256 + col] =
                        make_float2(acc[mi][ni][0] + bx, acc[mi][ni][1] + by);
                if (d1 >= 0)
                    *(float2*)&Cf[(long)b * strideC + (long)d1 * 256 + col] =
                        make_float2(acc[mi][ni][2] + bx, acc[mi][ni][3] + by);
            }
        }
    }
}

// ---------------- k_red1: reduce GEMM1 partials + bias, scatter into x2 ----------------
__global__ void __launch_bounds__(128) k_red1(const float* __restrict__ b1) {
    int row = blockIdx.x, b = blockIdx.y;
    int tgt = g_inv2[b * L2C + row];
    if (tgt < 0) return;
    int col = threadIdx.x * 2;
    float2 s = make_float2(b1[col], b1[col + 1]);
    #pragma unroll
    for (int sp = 0; sp < 4; sp++) {
        float2 v = *(const float2*)&g_part[(((long)sp * BB + b) * 1024 + row) * 256 + col];
        s.x += v.x; s.y += v.y;
    }
    __half h0, l0, h1, l1;
    split2h(s.x, h0, l0); split2h(s.y, h1, l1);
    long dst = ((long)b * L2C + tgt) * DC + col;
    *(__half2*)&g_x2hi[dst] = __halves2half2(h0, h1);
    *(__half2*)&g_x2lo[dst] = __halves2half2(l0, l1);
}

// ---------------- launch ----------------
extern "C" void kernel_launch(void* const* d_in, const int* in_sizes, int n_in,
                              void* d_out, int out_size) {
    (void)in_sizes; (void)n_in; (void)out_size;
    const int*   value    = (const int*)d_in[0];
    const int*   depth    = (const int*)d_in[1];
    const int*   position = (const int*)d_in[2];
    const float* emb_val  = (const float*)d_in[3];
    const float* emb_dep  = (const float*)d_in[4];
    const float* emb_pos  = (const float*)d_in[5];
    const float* W0 = (const float*)d_in[6];
    const float* b0 = (const float*)d_in[7];
    const float* W1 = (const float*)d_in[8];
    const float* b1 = (const float*)d_in[9];
    const float* W2 = (const float*)d_in[10];
    const float* b2 = (const float*)d_in[11];
    float* out = (float*)d_out;

    __half *w1, *w2, *x1h, *x1l, *x2h, *x2l;
    float *part;
    int *odst;
    cudaGetSymbolAddress((void**)&w1, g_W1);
    cudaGetSymbolAddress((void**)&w2, g_W2);
    cudaGetSymbolAddress((void**)&x1h, g_x1hi); cudaGetSymbolAddress((void**)&x1l, g_x1lo);
    cudaGetSymbolAddress((void**)&x2h, g_x2hi); cudaGetSymbolAddress((void**)&x2l, g_x2lo);
    cudaGetSymbolAddress((void**)&part, g_part);
    cudaGetSymbolAddress((void**)&odst, g_outdst);

    const int SMEM1 = 2 * ((2 * 64 + 256) * 128);   // 98304 (BM64,BN256, 2 stages)
    const int SMEM2 = 4 * ((2 * 64 + 64) * 128);    // 98304 (64x64, 4 stages)
    cudaFuncSetAttribute(k_prep1, cudaFuncAttributeMaxDynamicSharedMemorySize, PREP_SMEM);
    cudaFuncSetAttribute(k_gemm<64, 256, 512, 2048, 2, 3>, cudaFuncAttributeMaxDynamicSharedMemorySize, SMEM1);
    cudaFuncSetAttribute(k_gemm<64, 64, 1024, 1024, 4, 2>, cudaFuncAttributeMaxDynamicSharedMemorySize, SMEM2);

    // 1. prep1: indices + W0 transpose + embed(L1,L2) + W1/W2 fp16 + zero out
    k_prep1<<<PREP_GRID, 1024, PREP_SMEM>>>(value, depth, position,
                                            emb_val, emb_dep, emb_pos, W0, W1, W2, out);
    // 2. prep2: P tables (conv0 absorbed into embedding tables), fp16
    k_prep2<<<8 * 17, 256>>>(emb_val, emb_dep, emb_pos);
    // 3. y0 via fp16 table gathers, scattered directly into x1
    k_y0<<<dim3(L1C / 8, BB), 256>>>(value, depth, position, b0);
    // 4. GEMM1: 1024 x 2048 x 256 per batch, split-K x4 -> partials
    k_gemm<64, 256, 512, 2048, 2, 3><<<dim3(16, 4, BB), 256, SMEM1>>>(
        x1h, x1l, (long)L1C * DC, w1, nullptr, part, nullptr, 0);
    // 5. reduce partials + b1, scatter into x2
    k_red1<<<dim3(1024, BB), 128>>>(b1);
    // 6. GEMM2: 256 x 1024 x 256 per batch, scatter rows into out
    k_gemm<64, 64, 1024, 1024, 4, 2><<<dim3(4, 4, BB), 256, SMEM2>>>(
        x2h, x2l, (long)L2C * DC, w2, b2, out, odst, (long)(256 * 256));
}